// round 14
// baseline (speedup 1.0000x reference)
#include <cuda_runtime.h>
#include <cuda_fp16.h>
#include <math.h>
#include <stdint.h>

// Problem constants.
#define BATCH 4
#define NSEQ  1024
#define DMODEL 1024
#define DHID  1024
#define NHEAD 16
#define HDIM  64
#define ROWS  (BATCH * NSEQ)   // 4096
#define NKT   16               // K tiles of 64

// Scratch (device globals — no allocation allowed).
__device__ __half g_x16[ROWS * DMODEL];             // post PE+LN, fp16
__device__ __half g_w16[3 * DMODEL * DHID];         // W (k-major), fp16
__device__ __half g_q16[ROWS * DHID];               // Q (scaled 0.125*log2e)
__device__ __half g_k16[ROWS * DHID];
__device__ __half g_v16[ROWS * DHID];               // V, fp16, row-major

// ---------------------------------------------------------------------------
// Helpers (sm_80-compatible PTX only: cp.async, ldmatrix, mma.sync)
// ---------------------------------------------------------------------------
__device__ __forceinline__ uint32_t smem_u32(const void* p) {
    uint32_t a;
    asm("{ .reg .u64 t; cvta.to.shared.u64 t, %1; cvt.u32.u64 %0, t; }"
        : "=r"(a) : "l"(p));
    return a;
}
#define SW128(off) ((off) ^ (((off) >> 3) & 0x70))

__device__ __forceinline__ void cpa16(uint32_t dst, const void* src) {
    asm volatile("cp.async.cg.shared.global [%0], [%1], 16;" :: "r"(dst), "l"(src));
}
#define CP_COMMIT() asm volatile("cp.async.commit_group;" ::: "memory")
#define CP_WAIT(n)  asm volatile("cp.async.wait_group %0;" :: "n"(n) : "memory")

#define LDSM4(r0, r1, r2, r3, addr) \
    asm volatile("ldmatrix.sync.aligned.m8n8.x4.shared.b16 {%0,%1,%2,%3}, [%4];" \
                 : "=r"(r0), "=r"(r1), "=r"(r2), "=r"(r3) : "r"(addr))

#define LDSM4T(r0, r1, r2, r3, addr) \
    asm volatile("ldmatrix.sync.aligned.m8n8.x4.trans.shared.b16 {%0,%1,%2,%3}, [%4];" \
                 : "=r"(r0), "=r"(r1), "=r"(r2), "=r"(r3) : "r"(addr))

#define MMA16816(d, a, b0, b1) \
    asm volatile("mma.sync.aligned.m16n8k16.row.col.f32.f16.f16.f32 " \
                 "{%0,%1,%2,%3}, {%4,%5,%6,%7}, {%8,%9}, {%0,%1,%2,%3};" \
                 : "+f"((d)[0]), "+f"((d)[1]), "+f"((d)[2]), "+f"((d)[3]) \
                 : "r"((a)[0]), "r"((a)[1]), "r"((a)[2]), "r"((a)[3]), \
                   "r"(b0), "r"(b1))

#define EX2H2(x) asm("ex2.approx.f16x2 %0, %0;" : "+r"(x))

__device__ __forceinline__ uint32_t pack_h2(float a, float b) {
    __half2 h = __floats2half2_rn(a, b);
    return *(uint32_t*)&h;
}

// ---------------------------------------------------------------------------
// Kernel 1 (fused prep): blocks [0,4096) do PE+LN -> fp16 x;
// blocks [4096, 4096+1536) do straight coalesced W fp32->fp16 convert.
// ---------------------------------------------------------------------------
__global__ void __launch_bounds__(256) prep_kernel(
    const float* __restrict__ te,
    const float* __restrict__ gamma,
    const float* __restrict__ beta,
    const float* __restrict__ Wq,
    const float* __restrict__ Wk,
    const float* __restrict__ Wv)
{
    int tid = threadIdx.x;

    if (blockIdx.x < ROWS) {
        // ---- PE + LayerNorm ----
        __shared__ float sbuf[8], ssbuf[8];
        int row = blockIdx.x;
        int pos = row & (NSEQ - 1);

        const float* trow = te + (size_t)row * DMODEL;
        float4 v = *(const float4*)(trow + tid * 4);

        const float L2 = 13.287712379549449f;  // log2(10000)
        float e0 = (float)(4 * tid)     * (1.0f / (float)DMODEL);
        float e1 = (float)(4 * tid + 2) * (1.0f / (float)DMODEL);
        float ang0 = (float)pos * exp2f(-e0 * L2);
        float ang1 = (float)pos * exp2f(-e1 * L2);
        float s0, c0, s1, c1;
        __sincosf(ang0, &s0, &c0);
        __sincosf(ang1, &s1, &c1);
        float x[4];
        x[0] = v.x + s0; x[1] = v.y + c0; x[2] = v.z + s1; x[3] = v.w + c1;

        float s  = x[0] + x[1] + x[2] + x[3];
        float ss = x[0]*x[0] + x[1]*x[1] + x[2]*x[2] + x[3]*x[3];
        #pragma unroll
        for (int o = 16; o > 0; o >>= 1) {
            s  += __shfl_xor_sync(0xffffffffu, s,  o);
            ss += __shfl_xor_sync(0xffffffffu, ss, o);
        }
        int w = tid >> 5;
        if ((tid & 31) == 0) { sbuf[w] = s; ssbuf[w] = ss; }
        __syncthreads();
        if (tid < 32) {
            float a = (tid < 8) ? sbuf[tid]  : 0.0f;
            float b = (tid < 8) ? ssbuf[tid] : 0.0f;
            #pragma unroll
            for (int o = 4; o > 0; o >>= 1) {
                a += __shfl_xor_sync(0xffffffffu, a, o);
                b += __shfl_xor_sync(0xffffffffu, b, o);
            }
            if (tid == 0) { sbuf[0] = a; ssbuf[0] = b; }
        }
        __syncthreads();
        float mu   = sbuf[0]  * (1.0f / DMODEL);
        float var  = ssbuf[0] * (1.0f / DMODEL) - mu * mu;
        float rstd = rsqrtf(var + 1e-5f);

        uint2 o;
        o.x = pack_h2((x[0] - mu) * rstd * gamma[tid*4+0] + beta[tid*4+0],
                      (x[1] - mu) * rstd * gamma[tid*4+1] + beta[tid*4+1]);
        o.y = pack_h2((x[2] - mu) * rstd * gamma[tid*4+2] + beta[tid*4+2],
                      (x[3] - mu) * rstd * gamma[tid*4+3] + beta[tid*4+3]);
        *(uint2*)(g_x16 + (size_t)row * DMODEL + tid * 4) = o;
    } else {
        // ---- W fp32 -> fp16 straight convert ----
        int id = blockIdx.x - ROWS;            // 0..1535
        int z = id >> 9;
        size_t off = (size_t)(id & 511) * 2048 + (size_t)tid * 8;
        const float* W = (z == 0) ? Wq : (z == 1) ? Wk : Wv;
        float4 a = *(const float4*)(W + off);
        float4 b = *(const float4*)(W + off + 4);
        uint4 o;
        o.x = pack_h2(a.x, a.y);
        o.y = pack_h2(a.z, a.w);
        o.z = pack_h2(b.x, b.y);
        o.w = pack_h2(b.z, b.w);
        *(uint4*)(g_w16 + (size_t)z * DMODEL * DHID + off) = o;
    }
}

// ---------------------------------------------------------------------------
// Kernel 2: QKV GEMM via mma.sync fp16. 128x128 CTA tile, 4 warps (2x2),
// warp tile 64x64 (128 B LDSM per MMA), 2 CTAs/SM, 2-stage double buffer.
// W k-major consumed via ldmatrix.trans; its 64x128-col tile is staged as
// two 8KB halves (each 64 rows x 128 B) so the SW128 path is unchanged.
// Epilogue: q (scaled 0.125*log2e), k, v all -> fp16.
// ---------------------------------------------------------------------------
__device__ __forceinline__ void stage_a128(uint32_t dstbase,
                                           const __half* src, int tid)
{
    #pragma unroll
    for (int t = 0; t < 8; t++) {
        int id = t * 128 + tid;
        uint32_t row = (uint32_t)(id >> 3);
        uint32_t c = (uint32_t)(id & 7) * 16u;
        uint32_t off = row * 128u + c;
        cpa16(dstbase + SW128(off), (const char*)src + (size_t)row * (DMODEL * 2) + c);
    }
}

__device__ __forceinline__ void stage_w64(uint32_t dstbase,
                                          const __half* src, int tid)
{
    #pragma unroll
    for (int t = 0; t < 4; t++) {
        int id = t * 128 + tid;
        uint32_t row = (uint32_t)(id >> 3);
        uint32_t c = (uint32_t)(id & 7) * 16u;
        uint32_t off = row * 128u + c;
        cpa16(dstbase + SW128(off), (const char*)src + (size_t)row * (DHID * 2) + c);
    }
}

__global__ void __launch_bounds__(128, 2) qkv_mma_kernel(
    const float* __restrict__ bq,
    const float* __restrict__ bk,
    const float* __restrict__ bv)
{
    extern __shared__ __align__(16) char dynsm[];
    uint32_t smbase = smem_u32(dynsm);

    int tid = threadIdx.x;
    int wid = tid >> 5;
    int lane = tid & 31;
    int z = blockIdx.z;
    int m0 = blockIdx.y * 128;
    int n0 = blockIdx.x * 128;

    const __half* ax = g_x16 + (size_t)m0 * DMODEL;
    const __half* bw = g_w16 + (size_t)z * DMODEL * DHID + n0;
    const float* bias = (z == 0) ? bq : (z == 1) ? bk : bv;

    int warp_m = wid >> 1;   // 0..1, 64 rows
    int warp_n = wid & 1;    // 0..1, 64 cols

    // A fragment lane addressing (row-major m16k16).
    int a_row = warp_m * 64 + (lane & 7) + ((lane >> 3) & 1) * 8;
    uint32_t a_cb = (uint32_t)(((lane >> 4) & 1) * 16);
    uint32_t a_xor = (uint32_t)((lane & 7) * 16);

    // B fragment via ldmatrix.trans (k-major rows, 128B-row halves).
    int vg2 = lane >> 3;
    uint32_t b_rowt = (uint32_t)(((vg2 & 1) * 8) + (lane & 7));
    uint32_t b_colbt = (uint32_t)((vg2 >> 1) * 16);

    float acc[4][8][4];
    #pragma unroll
    for (int mi = 0; mi < 4; mi++)
        #pragma unroll
        for (int nj = 0; nj < 8; nj++)
            #pragma unroll
            for (int c = 0; c < 4; c++) acc[mi][nj][c] = 0.0f;

    const uint32_t STG = 32768u;   // A 16KB + B 16KB per stage
    stage_a128(smbase,                   ax, tid);
    stage_w64 (smbase + 16384u,          bw, tid);        // half 0: n [0,64)
    stage_w64 (smbase + 16384u + 8192u,  bw + 64, tid);   // half 1: n [64,128)
    CP_COMMIT();

    for (int kt = 0; kt < NKT; kt++) {
        if (kt + 1 < NKT) {
            uint32_t nb = smbase + (uint32_t)((kt + 1) & 1) * STG;
            int ko = (kt + 1) * 64;
            stage_a128(nb,                  ax + ko, tid);
            stage_w64 (nb + 16384u,         bw + (size_t)ko * DHID, tid);
            stage_w64 (nb + 16384u + 8192u, bw + (size_t)ko * DHID + 64, tid);
            CP_COMMIT();
            CP_WAIT(1);
        } else {
            CP_WAIT(0);
        }
        __syncthreads();

        uint32_t buf = smbase + (uint32_t)(kt & 1) * STG;
        uint32_t bufA = buf;
        uint32_t bufB = buf + 16384u + (uint32_t)warp_n * 8192u;  // this warp's half

        #pragma unroll
        for (int k16 = 0; k16 < 4; k16++) {
            uint32_t kca = (uint32_t)(k16 * 32) + a_cb;

            uint32_t af[4][4];
            #pragma unroll
            for (int mi = 0; mi < 4; mi++) {
                uint32_t roff = (uint32_t)(a_row + mi * 16) * 128u + (kca ^ a_xor);
                LDSM4(af[mi][0], af[mi][1], af[mi][2], af[mi][3], bufA + roff);
            }
            uint32_t bf[4][4];
            #pragma unroll
            for (int g = 0; g < 4; g++) {
                uint32_t off = ((uint32_t)(k16 * 16) + b_rowt) * 128u
                             + (uint32_t)(g * 32) + b_colbt;
                LDSM4T(bf[g][0], bf[g][1], bf[g][2], bf[g][3], bufB + SW128(off));
            }

            #pragma unroll
            for (int mi = 0; mi < 4; mi++) {
                #pragma unroll
                for (int g = 0; g < 4; g++) {
                    MMA16816(acc[mi][g * 2],     af[mi], bf[g][0], bf[g][1]);
                    MMA16816(acc[mi][g * 2 + 1], af[mi], bf[g][2], bf[g][3]);
                }
            }
        }
        __syncthreads();
    }

    // Epilogue: all three outputs fp16 (q scaled by 0.125*log2(e) for exp2).
    int er = lane >> 2;
    int ec = (lane & 3) * 2;
    float sc = (z == 0) ? (0.125f * 1.4426950408889634f) : 1.0f;
    uint32_t* out16 = (uint32_t*)((z == 0) ? g_q16 : (z == 1) ? g_k16 : g_v16);

    #pragma unroll
    for (int mi = 0; mi < 4; mi++) {
        int r0 = m0 + warp_m * 64 + mi * 16 + er;
        #pragma unroll
        for (int nj = 0; nj < 8; nj++) {
            int col = n0 + warp_n * 64 + nj * 8 + ec;
            float2 bb = *(const float2*)(bias + col);
            out16[((size_t)r0 * DHID + col) >> 1] =
                pack_h2((acc[mi][nj][0] + bb.x) * sc, (acc[mi][nj][1] + bb.y) * sc);
            out16[((size_t)(r0 + 8) * DHID + col) >> 1] =
                pack_h2((acc[mi][nj][2] + bb.x) * sc, (acc[mi][nj][3] + bb.y) * sc);
        }
    }
}

// ---------------------------------------------------------------------------
// Kernel 3: flash attention (R13 winner, unchanged). fp16x2 exp + ones-MMA
// row sums. CTA = 128 queries x one (b,h), 256 threads, 6-buffer K/V ring
// + Q at 96K, one barrier per TWO chunks, 112KB, 2 CTA/SM.
// ---------------------------------------------------------------------------
__device__ __forceinline__ void stage_rows(uint32_t dst, const __half* src,
                                           int total8, int tid, size_t stride)
{
    for (int id = tid; id < total8; id += 256) {
        uint32_t row = (uint32_t)(id >> 3);
        uint32_t seg = (uint32_t)(id & 7) * 16u;
        uint32_t off = row * 128u + seg;
        cpa16(dst + SW128(off), (const char*)src + (size_t)row * stride * 2 + seg);
    }
}

__global__ void __launch_bounds__(256, 2) flash_mma_kernel(float* __restrict__ out)
{
    extern __shared__ __align__(16) char dynsm[];
    uint32_t smbase = smem_u32(dynsm);

    int tid = threadIdx.x;
    int wid = tid >> 5;
    int lane = tid & 31;
    int bh = blockIdx.y;
    int b = bh >> 4, h = bh & 15;
    int q0 = blockIdx.x * 128;

    const __half* Qg = g_q16 + (size_t)(b * NSEQ + q0) * DHID + h * HDIM;
    const __half* Kg = g_k16 + (size_t)(b * NSEQ) * DHID + h * HDIM;
    const __half* Vg = g_v16 + (size_t)(b * NSEQ) * DHID + h * HDIM;

    const uint32_t QOFF = 98304u;   // 96 KB

    stage_rows(smbase + QOFF, Qg, 1024, tid, DHID);
    CP_COMMIT();
    #pragma unroll
    for (int c = 0; c < 4; c++) {
        uint32_t bf = smbase + (uint32_t)c * 16384u;
        stage_rows(bf,         Kg + (size_t)(c * 64) * DHID, 512, tid, DHID);
        stage_rows(bf + 8192u, Vg + (size_t)(c * 64) * DHID, 512, tid, DHID);
        CP_COMMIT();
    }

    CP_WAIT(4);
    __syncthreads();
    uint32_t qf[4][4];
    {
        int a_row = wid * 16 + (lane & 7) + ((lane >> 3) & 1) * 8;
        uint32_t a_cb = (uint32_t)(((lane >> 4) & 1) * 16);
        uint32_t a_xor = (uint32_t)((lane & 7) * 16);
        #pragma unroll
        for (int k16 = 0; k16 < 4; k16++) {
            uint32_t roff = (uint32_t)a_row * 128u + (((uint32_t)(k16 * 32) + a_cb) ^ a_xor);
            LDSM4(qf[k16][0], qf[k16][1], qf[k16][2], qf[k16][3],
                  smbase + QOFF + roff);
        }
    }

    int b_sub = (lane & 7) + ((lane >> 4) & 1) * 8;
    uint32_t b_cb = (uint32_t)(((lane >> 3) & 1) * 16);
    uint32_t b_xor = (uint32_t)((lane & 7) * 16);

    int vg2 = lane >> 3;
    uint32_t v_row = (uint32_t)(((vg2 & 1) * 8) + (lane & 7));
    uint32_t v_colb = (uint32_t)((vg2 >> 1) * 16);

    float O[8][4];
    #pragma unroll
    for (int dj = 0; dj < 8; dj++)
        #pragma unroll
        for (int c = 0; c < 4; c++) O[dj][c] = 0.0f;
    float Osum[4] = {0.0f, 0.0f, 0.0f, 0.0f};   // l via P @ ones
    const uint32_t ONES = 0x3C003C00u;          // fp16x2 (1.0, 1.0)

    for (int p = 0; p < 8; p++) {
        if (p < 7) { CP_WAIT(2); } else { CP_WAIT(0); }
        __syncthreads();

        if (p < 6) {
            #pragma unroll
            for (int s = 0; s < 2; s++) {
                int c = 2 * p + 4 + s;
                uint32_t bf = smbase + (uint32_t)(c % 6) * 16384u;
                stage_rows(bf,         Kg + (size_t)(c * 64) * DHID, 512, tid, DHID);
                stage_rows(bf + 8192u, Vg + (size_t)(c * 64) * DHID, 512, tid, DHID);
                CP_COMMIT();
            }
        }

        #pragma unroll
        for (int h2 = 0; h2 < 2; h2++) {
            int kt = 2 * p + h2;
            uint32_t buf = smbase + (uint32_t)(kt % 6) * 16384u;
            uint32_t bK = buf, bV = buf + 8192u;

            // ---- S = Q K^T (Q pre-scaled by 0.125*log2e) ----
            float S[8][4];
            #pragma unroll
            for (int nj = 0; nj < 8; nj++)
                #pragma unroll
                for (int c = 0; c < 4; c++) S[nj][c] = 0.0f;

            #pragma unroll
            for (int k16 = 0; k16 < 4; k16++) {
                uint32_t kc = ((uint32_t)(k16 * 32) + b_cb) ^ b_xor;
                #pragma unroll
                for (int ng = 0; ng < 4; ng++) {
                    uint32_t roff = (uint32_t)(b_sub + ng * 16) * 128u + kc;
                    uint32_t kf[4];
                    LDSM4(kf[0], kf[1], kf[2], kf[3], bK + roff);
                    MMA16816(S[ng * 2],     qf[k16], kf[0], kf[1]);
                    MMA16816(S[ng * 2 + 1], qf[k16], kf[2], kf[3]);
                }
            }

            // ---- pack to fp16 pairs, then ex2.approx.f16x2 (P directly) ----
            uint32_t pf[4][4];
            #pragma unroll
            for (int j = 0; j < 4; j++) {
                pf[j][0] = pack_h2(S[2*j][0],   S[2*j][1]);   EX2H2(pf[j][0]);
                pf[j][1] = pack_h2(S[2*j][2],   S[2*j][3]);   EX2H2(pf[j][1]);
                pf[j][2] = pack_h2(S[2*j+1][0], S[2*j+1][1]); EX2H2(pf[j][2]);
                pf[j][3] = pack_h2(S[2*j+1][2], S[2*j+1][3]); EX2H2(pf[j][3]);
            }

            // ---- O += P V (V row-major, ldmatrix.trans); l += P @ ones ----
            #pragma unroll
            for (int k16 = 0; k16 < 4; k16++) {
                uint32_t rbase = (uint32_t)(k16 * 16) + v_row;
                #pragma unroll
                for (int dg = 0; dg < 4; dg++) {
                    uint32_t off = rbase * 128u + (uint32_t)(dg * 32) + v_colb;
                    uint32_t vf[4];
                    LDSM4T(vf[0], vf[1], vf[2], vf[3], bV + SW128(off));
                    MMA16816(O[dg * 2],     pf[k16], vf[0], vf[1]);
                    MMA16816(O[dg * 2 + 1], pf[k16], vf[2], vf[3]);
                }
                MMA16816(Osum, pf[k16], ONES, ONES);
            }
        }
    }

    float inv0 = 1.0f / Osum[0], inv1 = 1.0f / Osum[2];

    int g = lane >> 2, t = lane & 3;
    int qrow = q0 + wid * 16 + g;
    #pragma unroll
    for (int dj = 0; dj < 8; dj++) {
        int col = h * HDIM + dj * 8 + 2 * t;
        *(float2*)(out + (size_t)(b * NSEQ + qrow) * DHID + col) =
            make_float2(O[dj][0] * inv0, O[dj][1] * inv0);
        *(float2*)(out + (size_t)(b * NSEQ + qrow + 8) * DHID + col) =
            make_float2(O[dj][2] * inv1, O[dj][3] * inv1);
    }
}

// ---------------------------------------------------------------------------
extern "C" void kernel_launch(void* const* d_in, const int* in_sizes, int n_in,
                              void* d_out, int out_size)
{
    const float* te    = (const float*)d_in[0];
    const float* gamma = (const float*)d_in[1];
    const float* beta  = (const float*)d_in[2];
    const float* Wq    = (const float*)d_in[3];
    const float* bq    = (const float*)d_in[4];
    const float* Wk    = (const float*)d_in[5];
    const float* bk    = (const float*)d_in[6];
    const float* Wv    = (const float*)d_in[7];
    const float* bv    = (const float*)d_in[8];
    float* out = (float*)d_out;

    prep_kernel<<<ROWS + 1536, 256>>>(te, gamma, beta, Wq, Wk, Wv);

    int gemm_smem = 2 * 32768;   // 64 KB
    cudaFuncSetAttribute(qkv_mma_kernel, cudaFuncAttributeMaxDynamicSharedMemorySize,
                         gemm_smem);
    qkv_mma_kernel<<<dim3(DHID / 128, ROWS / 128, 3), 128, gemm_smem>>>(bq, bk, bv);

    int flash_smem = 114688;     // 6 x 16KB ring + 16KB Q = 112 KB
    cudaFuncSetAttribute(flash_mma_kernel, cudaFuncAttributeMaxDynamicSharedMemorySize,
                         flash_smem);
    flash_mma_kernel<<<dim3(NSEQ / 128, BATCH * NHEAD), 256, flash_smem>>>(out);
}

// round 15
// speedup vs baseline: 1.0191x; 1.0191x over previous
#include <cuda_runtime.h>
#include <cuda_fp16.h>
#include <math.h>
#include <stdint.h>

// Problem constants.
#define BATCH 4
#define NSEQ  1024
#define DMODEL 1024
#define DHID  1024
#define NHEAD 16
#define HDIM  64
#define ROWS  (BATCH * NSEQ)   // 4096
#define NKT   16               // K tiles of 64

// Scratch (device globals — no allocation allowed).
__device__ __half g_x16[ROWS * DMODEL];             // post PE+LN, fp16
__device__ __half g_w16[3 * DMODEL * DHID];         // W (k-major), fp16
__device__ __half g_q16[ROWS * DHID];               // Q (scaled 0.125*log2e)
__device__ __half g_k16[ROWS * DHID];
__device__ __half g_v16[ROWS * DHID];               // V, fp16, row-major

// ---------------------------------------------------------------------------
// Helpers (sm_80-compatible PTX only: cp.async, ldmatrix, mma.sync)
// ---------------------------------------------------------------------------
__device__ __forceinline__ uint32_t smem_u32(const void* p) {
    uint32_t a;
    asm("{ .reg .u64 t; cvta.to.shared.u64 t, %1; cvt.u32.u64 %0, t; }"
        : "=r"(a) : "l"(p));
    return a;
}
#define SW128(off) ((off) ^ (((off) >> 3) & 0x70))

__device__ __forceinline__ void cpa16(uint32_t dst, const void* src) {
    asm volatile("cp.async.cg.shared.global [%0], [%1], 16;" :: "r"(dst), "l"(src));
}
#define CP_COMMIT() asm volatile("cp.async.commit_group;" ::: "memory")
#define CP_WAIT(n)  asm volatile("cp.async.wait_group %0;" :: "n"(n) : "memory")

#define LDSM4(r0, r1, r2, r3, addr) \
    asm volatile("ldmatrix.sync.aligned.m8n8.x4.shared.b16 {%0,%1,%2,%3}, [%4];" \
                 : "=r"(r0), "=r"(r1), "=r"(r2), "=r"(r3) : "r"(addr))

#define LDSM4T(r0, r1, r2, r3, addr) \
    asm volatile("ldmatrix.sync.aligned.m8n8.x4.trans.shared.b16 {%0,%1,%2,%3}, [%4];" \
                 : "=r"(r0), "=r"(r1), "=r"(r2), "=r"(r3) : "r"(addr))

#define MMA16816(d, a, b0, b1) \
    asm volatile("mma.sync.aligned.m16n8k16.row.col.f32.f16.f16.f32 " \
                 "{%0,%1,%2,%3}, {%4,%5,%6,%7}, {%8,%9}, {%0,%1,%2,%3};" \
                 : "+f"((d)[0]), "+f"((d)[1]), "+f"((d)[2]), "+f"((d)[3]) \
                 : "r"((a)[0]), "r"((a)[1]), "r"((a)[2]), "r"((a)[3]), \
                   "r"(b0), "r"(b1))

#define EX2H2(x) asm("ex2.approx.f16x2 %0, %0;" : "+r"(x))

__device__ __forceinline__ uint32_t pack_h2(float a, float b) {
    __half2 h = __floats2half2_rn(a, b);
    return *(uint32_t*)&h;
}

// ---------------------------------------------------------------------------
// Kernel 1 (fused prep):
//  blocks [0, 2048): PE+LN for TWO rows each (MLP=2 on the te loads);
//  blocks [2048, 2048+768): W fp32->fp16 convert, 16 elems/thread (MLP=4).
// ---------------------------------------------------------------------------
__global__ void __launch_bounds__(256) prep_kernel(
    const float* __restrict__ te,
    const float* __restrict__ gamma,
    const float* __restrict__ beta,
    const float* __restrict__ Wq,
    const float* __restrict__ Wk,
    const float* __restrict__ Wv)
{
    int tid = threadIdx.x;

    if (blockIdx.x < ROWS / 2) {
        // ---- PE + LayerNorm, two rows per block ----
        __shared__ float sb0[8], sq0[8], sb1[8], sq1[8];
        int row0 = blockIdx.x * 2;
        int row1 = row0 + 1;
        int pos0 = row0 & (NSEQ - 1);
        int pos1 = row1 & (NSEQ - 1);

        // Two independent loads issued back-to-back (MLP=2).
        float4 v0 = *(const float4*)(te + (size_t)row0 * DMODEL + tid * 4);
        float4 v1 = *(const float4*)(te + (size_t)row1 * DMODEL + tid * 4);

        const float L2 = 13.287712379549449f;  // log2(10000)
        float e0 = (float)(4 * tid)     * (1.0f / (float)DMODEL);
        float e1 = (float)(4 * tid + 2) * (1.0f / (float)DMODEL);
        float f0 = exp2f(-e0 * L2);             // inverse frequencies (shared)
        float f1 = exp2f(-e1 * L2);

        float s0a, c0a, s1a, c1a, s0b, c0b, s1b, c1b;
        __sincosf((float)pos0 * f0, &s0a, &c0a);
        __sincosf((float)pos0 * f1, &s1a, &c1a);
        __sincosf((float)pos1 * f0, &s0b, &c0b);
        __sincosf((float)pos1 * f1, &s1b, &c1b);

        float x0[4], x1[4];
        x0[0] = v0.x + s0a; x0[1] = v0.y + c0a; x0[2] = v0.z + s1a; x0[3] = v0.w + c1a;
        x1[0] = v1.x + s0b; x1[1] = v1.y + c0b; x1[2] = v1.z + s1b; x1[3] = v1.w + c1b;

        float sA  = x0[0] + x0[1] + x0[2] + x0[3];
        float qA  = x0[0]*x0[0] + x0[1]*x0[1] + x0[2]*x0[2] + x0[3]*x0[3];
        float sB  = x1[0] + x1[1] + x1[2] + x1[3];
        float qB  = x1[0]*x1[0] + x1[1]*x1[1] + x1[2]*x1[2] + x1[3]*x1[3];
        #pragma unroll
        for (int o = 16; o > 0; o >>= 1) {
            sA += __shfl_xor_sync(0xffffffffu, sA, o);
            qA += __shfl_xor_sync(0xffffffffu, qA, o);
            sB += __shfl_xor_sync(0xffffffffu, sB, o);
            qB += __shfl_xor_sync(0xffffffffu, qB, o);
        }
        int w = tid >> 5;
        if ((tid & 31) == 0) { sb0[w] = sA; sq0[w] = qA; sb1[w] = sB; sq1[w] = qB; }
        __syncthreads();
        if (tid < 32) {
            float a = (tid < 8) ? sb0[tid] : 0.0f;
            float b = (tid < 8) ? sq0[tid] : 0.0f;
            float c = (tid < 8) ? sb1[tid] : 0.0f;
            float d = (tid < 8) ? sq1[tid] : 0.0f;
            #pragma unroll
            for (int o = 4; o > 0; o >>= 1) {
                a += __shfl_xor_sync(0xffffffffu, a, o);
                b += __shfl_xor_sync(0xffffffffu, b, o);
                c += __shfl_xor_sync(0xffffffffu, c, o);
                d += __shfl_xor_sync(0xffffffffu, d, o);
            }
            if (tid == 0) { sb0[0] = a; sq0[0] = b; sb1[0] = c; sq1[0] = d; }
        }
        __syncthreads();
        float muA  = sb0[0] * (1.0f / DMODEL);
        float rstdA = rsqrtf(sq0[0] * (1.0f / DMODEL) - muA * muA + 1e-5f);
        float muB  = sb1[0] * (1.0f / DMODEL);
        float rstdB = rsqrtf(sq1[0] * (1.0f / DMODEL) - muB * muB + 1e-5f);

        float g0 = gamma[tid*4+0], g1 = gamma[tid*4+1];
        float g2 = gamma[tid*4+2], g3 = gamma[tid*4+3];
        float b0 = beta[tid*4+0],  b1 = beta[tid*4+1];
        float b2 = beta[tid*4+2],  b3 = beta[tid*4+3];

        uint2 oA, oB;
        oA.x = pack_h2((x0[0] - muA) * rstdA * g0 + b0,
                       (x0[1] - muA) * rstdA * g1 + b1);
        oA.y = pack_h2((x0[2] - muA) * rstdA * g2 + b2,
                       (x0[3] - muA) * rstdA * g3 + b3);
        oB.x = pack_h2((x1[0] - muB) * rstdB * g0 + b0,
                       (x1[1] - muB) * rstdB * g1 + b1);
        oB.y = pack_h2((x1[2] - muB) * rstdB * g2 + b2,
                       (x1[3] - muB) * rstdB * g3 + b3);
        *(uint2*)(g_x16 + (size_t)row0 * DMODEL + tid * 4) = oA;
        *(uint2*)(g_x16 + (size_t)row1 * DMODEL + tid * 4) = oB;
    } else {
        // ---- W fp32 -> fp16 convert, 16 elems/thread (MLP=4) ----
        int id = blockIdx.x - ROWS / 2;        // 0..767
        int z = id >> 8;                       // 256 blocks per matrix
        size_t off = (size_t)(id & 255) * 4096 + (size_t)tid * 16;
        const float* W = (z == 0) ? Wq : (z == 1) ? Wk : Wv;
        float4 a = *(const float4*)(W + off);
        float4 b = *(const float4*)(W + off + 4);
        float4 c = *(const float4*)(W + off + 8);
        float4 d = *(const float4*)(W + off + 12);
        uint4 o1, o2;
        o1.x = pack_h2(a.x, a.y);
        o1.y = pack_h2(a.z, a.w);
        o1.z = pack_h2(b.x, b.y);
        o1.w = pack_h2(b.z, b.w);
        o2.x = pack_h2(c.x, c.y);
        o2.y = pack_h2(c.z, c.w);
        o2.z = pack_h2(d.x, d.y);
        o2.w = pack_h2(d.z, d.w);
        __half* dst = g_w16 + (size_t)z * DMODEL * DHID + off;
        *(uint4*)dst       = o1;
        *(uint4*)(dst + 8) = o2;
    }
}

// ---------------------------------------------------------------------------
// Kernel 2: QKV GEMM via mma.sync fp16 (R10/R13 champion config).
// 128x64 CTA tile, 4 warps (2x2, warp tile 64x32), 4 CTAs/SM, 2-stage
// double buffer, W k-major via ldmatrix.trans.
// Epilogue: q (scaled 0.125*log2e), k, v all -> fp16.
// ---------------------------------------------------------------------------
__device__ __forceinline__ void stage_a128(uint32_t dstbase,
                                           const __half* src, int tid)
{
    #pragma unroll
    for (int t = 0; t < 8; t++) {
        int id = t * 128 + tid;
        uint32_t row = (uint32_t)(id >> 3);
        uint32_t c = (uint32_t)(id & 7) * 16u;
        uint32_t off = row * 128u + c;
        cpa16(dstbase + SW128(off), (const char*)src + (size_t)row * (DMODEL * 2) + c);
    }
}

__device__ __forceinline__ void stage_w64(uint32_t dstbase,
                                          const __half* src, int tid)
{
    #pragma unroll
    for (int t = 0; t < 4; t++) {
        int id = t * 128 + tid;
        uint32_t row = (uint32_t)(id >> 3);
        uint32_t c = (uint32_t)(id & 7) * 16u;
        uint32_t off = row * 128u + c;
        cpa16(dstbase + SW128(off), (const char*)src + (size_t)row * (DHID * 2) + c);
    }
}

__global__ void __launch_bounds__(128, 4) qkv_mma_kernel(
    const float* __restrict__ bq,
    const float* __restrict__ bk,
    const float* __restrict__ bv)
{
    extern __shared__ __align__(16) char dynsm[];
    uint32_t smbase = smem_u32(dynsm);

    int tid = threadIdx.x;
    int wid = tid >> 5;
    int lane = tid & 31;
    int z = blockIdx.z;
    int m0 = blockIdx.y * 128;
    int n0 = blockIdx.x * 64;

    const __half* ax = g_x16 + (size_t)m0 * DMODEL;
    const __half* bw = g_w16 + (size_t)z * DMODEL * DHID + n0;
    const float* bias = (z == 0) ? bq : (z == 1) ? bk : bv;

    int warp_m = wid >> 1;
    int warp_n = wid & 1;

    int a_row = warp_m * 64 + (lane & 7) + ((lane >> 3) & 1) * 8;
    uint32_t a_cb = (uint32_t)(((lane >> 4) & 1) * 16);
    uint32_t a_xor = (uint32_t)((lane & 7) * 16);

    int vg2 = lane >> 3;
    uint32_t b_rowt = (uint32_t)(((vg2 & 1) * 8) + (lane & 7));
    uint32_t b_colbt = (uint32_t)((vg2 >> 1) * 16);

    float acc[4][4][4];
    #pragma unroll
    for (int mi = 0; mi < 4; mi++)
        #pragma unroll
        for (int nj = 0; nj < 4; nj++)
            #pragma unroll
            for (int c = 0; c < 4; c++) acc[mi][nj][c] = 0.0f;

    const uint32_t STG = 24576u;
    stage_a128(smbase,          ax, tid);
    stage_w64 (smbase + 16384u, bw, tid);
    CP_COMMIT();

    for (int kt = 0; kt < NKT; kt++) {
        if (kt + 1 < NKT) {
            uint32_t nb = smbase + (uint32_t)((kt + 1) & 1) * STG;
            int ko = (kt + 1) * 64;
            stage_a128(nb,          ax + ko, tid);
            stage_w64 (nb + 16384u, bw + (size_t)ko * DHID, tid);
            CP_COMMIT();
            CP_WAIT(1);
        } else {
            CP_WAIT(0);
        }
        __syncthreads();

        uint32_t buf = smbase + (uint32_t)(kt & 1) * STG;
        uint32_t bufA = buf, bufB = buf + 16384u;

        #pragma unroll
        for (int k16 = 0; k16 < 4; k16++) {
            uint32_t kca = (uint32_t)(k16 * 32) + a_cb;

            uint32_t af[4][4];
            #pragma unroll
            for (int mi = 0; mi < 4; mi++) {
                uint32_t roff = (uint32_t)(a_row + mi * 16) * 128u + (kca ^ a_xor);
                LDSM4(af[mi][0], af[mi][1], af[mi][2], af[mi][3], bufA + roff);
            }
            uint32_t bf[2][4];
            #pragma unroll
            for (int g = 0; g < 2; g++) {
                uint32_t off = ((uint32_t)(k16 * 16) + b_rowt) * 128u
                             + (uint32_t)(warp_n * 64 + g * 32) + b_colbt;
                LDSM4T(bf[g][0], bf[g][1], bf[g][2], bf[g][3], bufB + SW128(off));
            }

            #pragma unroll
            for (int mi = 0; mi < 4; mi++) {
                #pragma unroll
                for (int g = 0; g < 2; g++) {
                    MMA16816(acc[mi][g * 2],     af[mi], bf[g][0], bf[g][1]);
                    MMA16816(acc[mi][g * 2 + 1], af[mi], bf[g][2], bf[g][3]);
                }
            }
        }
        __syncthreads();
    }

    int er = lane >> 2;
    int ec = (lane & 3) * 2;
    float sc = (z == 0) ? (0.125f * 1.4426950408889634f) : 1.0f;
    uint32_t* out16 = (uint32_t*)((z == 0) ? g_q16 : (z == 1) ? g_k16 : g_v16);

    #pragma unroll
    for (int mi = 0; mi < 4; mi++) {
        int r0 = m0 + warp_m * 64 + mi * 16 + er;
        #pragma unroll
        for (int nj = 0; nj < 4; nj++) {
            int col = n0 + warp_n * 32 + nj * 8 + ec;
            float2 bb = *(const float2*)(bias + col);
            out16[((size_t)r0 * DHID + col) >> 1] =
                pack_h2((acc[mi][nj][0] + bb.x) * sc, (acc[mi][nj][1] + bb.y) * sc);
            out16[((size_t)(r0 + 8) * DHID + col) >> 1] =
                pack_h2((acc[mi][nj][2] + bb.x) * sc, (acc[mi][nj][3] + bb.y) * sc);
        }
    }
}

// ---------------------------------------------------------------------------
// Kernel 3: flash attention (R13 winner, unchanged). fp16x2 exp + ones-MMA
// row sums. CTA = 128 queries x one (b,h), 256 threads, 6-buffer K/V ring
// + Q at 96K, one barrier per TWO chunks, 112KB, 2 CTA/SM.
// ---------------------------------------------------------------------------
__device__ __forceinline__ void stage_rows(uint32_t dst, const __half* src,
                                           int total8, int tid, size_t stride)
{
    for (int id = tid; id < total8; id += 256) {
        uint32_t row = (uint32_t)(id >> 3);
        uint32_t seg = (uint32_t)(id & 7) * 16u;
        uint32_t off = row * 128u + seg;
        cpa16(dst + SW128(off), (const char*)src + (size_t)row * stride * 2 + seg);
    }
}

__global__ void __launch_bounds__(256, 2) flash_mma_kernel(float* __restrict__ out)
{
    extern __shared__ __align__(16) char dynsm[];
    uint32_t smbase = smem_u32(dynsm);

    int tid = threadIdx.x;
    int wid = tid >> 5;
    int lane = tid & 31;
    int bh = blockIdx.y;
    int b = bh >> 4, h = bh & 15;
    int q0 = blockIdx.x * 128;

    const __half* Qg = g_q16 + (size_t)(b * NSEQ + q0) * DHID + h * HDIM;
    const __half* Kg = g_k16 + (size_t)(b * NSEQ) * DHID + h * HDIM;
    const __half* Vg = g_v16 + (size_t)(b * NSEQ) * DHID + h * HDIM;

    const uint32_t QOFF = 98304u;   // 96 KB

    stage_rows(smbase + QOFF, Qg, 1024, tid, DHID);
    CP_COMMIT();
    #pragma unroll
    for (int c = 0; c < 4; c++) {
        uint32_t bf = smbase + (uint32_t)c * 16384u;
        stage_rows(bf,         Kg + (size_t)(c * 64) * DHID, 512, tid, DHID);
        stage_rows(bf + 8192u, Vg + (size_t)(c * 64) * DHID, 512, tid, DHID);
        CP_COMMIT();
    }

    CP_WAIT(4);
    __syncthreads();
    uint32_t qf[4][4];
    {
        int a_row = wid * 16 + (lane & 7) + ((lane >> 3) & 1) * 8;
        uint32_t a_cb = (uint32_t)(((lane >> 4) & 1) * 16);
        uint32_t a_xor = (uint32_t)((lane & 7) * 16);
        #pragma unroll
        for (int k16 = 0; k16 < 4; k16++) {
            uint32_t roff = (uint32_t)a_row * 128u + (((uint32_t)(k16 * 32) + a_cb) ^ a_xor);
            LDSM4(qf[k16][0], qf[k16][1], qf[k16][2], qf[k16][3],
                  smbase + QOFF + roff);
        }
    }

    int b_sub = (lane & 7) + ((lane >> 4) & 1) * 8;
    uint32_t b_cb = (uint32_t)(((lane >> 3) & 1) * 16);
    uint32_t b_xor = (uint32_t)((lane & 7) * 16);

    int vg2 = lane >> 3;
    uint32_t v_row = (uint32_t)(((vg2 & 1) * 8) + (lane & 7));
    uint32_t v_colb = (uint32_t)((vg2 >> 1) * 16);

    float O[8][4];
    #pragma unroll
    for (int dj = 0; dj < 8; dj++)
        #pragma unroll
        for (int c = 0; c < 4; c++) O[dj][c] = 0.0f;
    float Osum[4] = {0.0f, 0.0f, 0.0f, 0.0f};   // l via P @ ones
    const uint32_t ONES = 0x3C003C00u;          // fp16x2 (1.0, 1.0)

    for (int p = 0; p < 8; p++) {
        if (p < 7) { CP_WAIT(2); } else { CP_WAIT(0); }
        __syncthreads();

        if (p < 6) {
            #pragma unroll
            for (int s = 0; s < 2; s++) {
                int c = 2 * p + 4 + s;
                uint32_t bf = smbase + (uint32_t)(c % 6) * 16384u;
                stage_rows(bf,         Kg + (size_t)(c * 64) * DHID, 512, tid, DHID);
                stage_rows(bf + 8192u, Vg + (size_t)(c * 64) * DHID, 512, tid, DHID);
                CP_COMMIT();
            }
        }

        #pragma unroll
        for (int h2 = 0; h2 < 2; h2++) {
            int kt = 2 * p + h2;
            uint32_t buf = smbase + (uint32_t)(kt % 6) * 16384u;
            uint32_t bK = buf, bV = buf + 8192u;

            // ---- S = Q K^T (Q pre-scaled by 0.125*log2e) ----
            float S[8][4];
            #pragma unroll
            for (int nj = 0; nj < 8; nj++)
                #pragma unroll
                for (int c = 0; c < 4; c++) S[nj][c] = 0.0f;

            #pragma unroll
            for (int k16 = 0; k16 < 4; k16++) {
                uint32_t kc = ((uint32_t)(k16 * 32) + b_cb) ^ b_xor;
                #pragma unroll
                for (int ng = 0; ng < 4; ng++) {
                    uint32_t roff = (uint32_t)(b_sub + ng * 16) * 128u + kc;
                    uint32_t kf[4];
                    LDSM4(kf[0], kf[1], kf[2], kf[3], bK + roff);
                    MMA16816(S[ng * 2],     qf[k16], kf[0], kf[1]);
                    MMA16816(S[ng * 2 + 1], qf[k16], kf[2], kf[3]);
                }
            }

            // ---- pack to fp16 pairs, then ex2.approx.f16x2 (P directly) ----
            uint32_t pf[4][4];
            #pragma unroll
            for (int j = 0; j < 4; j++) {
                pf[j][0] = pack_h2(S[2*j][0],   S[2*j][1]);   EX2H2(pf[j][0]);
                pf[j][1] = pack_h2(S[2*j][2],   S[2*j][3]);   EX2H2(pf[j][1]);
                pf[j][2] = pack_h2(S[2*j+1][0], S[2*j+1][1]); EX2H2(pf[j][2]);
                pf[j][3] = pack_h2(S[2*j+1][2], S[2*j+1][3]); EX2H2(pf[j][3]);
            }

            // ---- O += P V (V row-major, ldmatrix.trans); l += P @ ones ----
            #pragma unroll
            for (int k16 = 0; k16 < 4; k16++) {
                uint32_t rbase = (uint32_t)(k16 * 16) + v_row;
                #pragma unroll
                for (int dg = 0; dg < 4; dg++) {
                    uint32_t off = rbase * 128u + (uint32_t)(dg * 32) + v_colb;
                    uint32_t vf[4];
                    LDSM4T(vf[0], vf[1], vf[2], vf[3], bV + SW128(off));
                    MMA16816(O[dg * 2],     pf[k16], vf[0], vf[1]);
                    MMA16816(O[dg * 2 + 1], pf[k16], vf[2], vf[3]);
                }
                MMA16816(Osum, pf[k16], ONES, ONES);
            }
        }
    }

    float inv0 = 1.0f / Osum[0], inv1 = 1.0f / Osum[2];

    int g = lane >> 2, t = lane & 3;
    int qrow = q0 + wid * 16 + g;
    #pragma unroll
    for (int dj = 0; dj < 8; dj++) {
        int col = h * HDIM + dj * 8 + 2 * t;
        *(float2*)(out + (size_t)(b * NSEQ + qrow) * DHID + col) =
            make_float2(O[dj][0] * inv0, O[dj][1] * inv0);
        *(float2*)(out + (size_t)(b * NSEQ + qrow + 8) * DHID + col) =
            make_float2(O[dj][2] * inv1, O[dj][3] * inv1);
    }
}

// ---------------------------------------------------------------------------
extern "C" void kernel_launch(void* const* d_in, const int* in_sizes, int n_in,
                              void* d_out, int out_size)
{
    const float* te    = (const float*)d_in[0];
    const float* gamma = (const float*)d_in[1];
    const float* beta  = (const float*)d_in[2];
    const float* Wq    = (const float*)d_in[3];
    const float* bq    = (const float*)d_in[4];
    const float* Wk    = (const float*)d_in[5];
    const float* bk    = (const float*)d_in[6];
    const float* Wv    = (const float*)d_in[7];
    const float* bv    = (const float*)d_in[8];
    float* out = (float*)d_out;

    prep_kernel<<<ROWS / 2 + 768, 256>>>(te, gamma, beta, Wq, Wk, Wv);

    int gemm_smem = 2 * 24576;   // 48 KB
    cudaFuncSetAttribute(qkv_mma_kernel, cudaFuncAttributeMaxDynamicSharedMemorySize,
                         gemm_smem);
    qkv_mma_kernel<<<dim3(DHID / 64, ROWS / 128, 3), 128, gemm_smem>>>(bq, bk, bv);

    int flash_smem = 114688;     // 6 x 16KB ring + 16KB Q = 112 KB
    cudaFuncSetAttribute(flash_mma_kernel, cudaFuncAttributeMaxDynamicSharedMemorySize,
                         flash_smem);
    flash_mma_kernel<<<dim3(NSEQ / 128, BATCH * NHEAD), 256, flash_smem>>>(out);
}